// round 1
// baseline (speedup 1.0000x reference)
#include <cuda_runtime.h>

#define B_DIM 1024
#define T_DIM 256
#define D_DIM 64
#define H_DIM 128
#define GH 256          // 2H
#define XCOLS 384       // 256 gate cols + 128 cand cols
#define RROWS 4
#define NGROUPS (B_DIM / RROWS)   // 256
#define KPAD 132        // padded k-stride for bank-conflict-free LDS.128

// Scratch (device globals: no allocation allowed). Zero-initialized at load.
static __device__ float g_Xbuf[(size_t)B_DIM * T_DIM * XCOLS]; // ~402 MB
static __device__ int   g_perm[B_DIM];
static __device__ int   g_counter;

__device__ __forceinline__ float fast_sigmoid(float z) {
    return __fdividef(1.0f, 1.0f + __expf(-z));
}
__device__ __forceinline__ float fast_tanh(float z) {
    return 1.0f - __fdividef(2.0f, __expf(2.0f * z) + 1.0f);
}

// ---------------------------------------------------------------------------
// K0: counting sort rows by seq_len (descending) + reset work counter.
// Output determinism: per-row math is identical regardless of grouping.
// ---------------------------------------------------------------------------
__global__ void sort_kernel(const int* __restrict__ seq_lens) {
    __shared__ int hist[256];
    __shared__ int offs[256];
    int tid = threadIdx.x;
    hist[tid] = 0;
    __syncthreads();
    for (int r = tid; r < B_DIM; r += 256) {
        int L = seq_lens[r];
        L = min(max(L, 0), 255);
        atomicAdd(&hist[L], 1);
    }
    __syncthreads();
    if (tid == 0) {
        int run = 0;
        for (int k = 255; k >= 0; k--) { offs[k] = run; run += hist[k]; }
        g_counter = 0;
    }
    __syncthreads();
    for (int r = tid; r < B_DIM; r += 256) {
        int L = seq_lens[r];
        L = min(max(L, 0), 255);
        int pos = atomicAdd(&offs[L], 1);
        g_perm[pos] = r;
    }
}

// ---------------------------------------------------------------------------
// K1: projection  Xbuf[b,t,0:256]   = emb[item] @ Wg_x + gate_bias
//                 Xbuf[b,t,256:384] = emb[item] @ Wc_x + cand_bias
// Only tiles with t0 < seq_len[b] are computed (rest never read / masked).
// Block = 256 threads, tile = 32 t-rows x 384 cols, fp32.
// ---------------------------------------------------------------------------
__global__ void __launch_bounds__(256) proj_kernel(
    const int* __restrict__ item_his,
    const int* __restrict__ seq_lens,
    const float* __restrict__ embedding,
    const float* __restrict__ gate_kernel,
    const float* __restrict__ gate_bias,
    const float* __restrict__ cand_kernel,
    const float* __restrict__ cand_bias)
{
    extern __shared__ float sm[];
    float* Wx = sm;                    // [64][384]
    float* xs = Wx + 64 * XCOLS;       // [32][64]
    float* bs = xs + 32 * 64;          // [384]
    __shared__ int items_s[32];

    int b  = blockIdx.y;
    int t0 = blockIdx.x * 32;
    int len = seq_lens[b];
    if (t0 >= len) return;
    int tid = threadIdx.x;

    // stage x-part weights (first 64 rows of each kernel) + biases
    for (int idx = tid; idx < 64 * GH; idx += 256) {
        int k = idx >> 8, c = idx & 255;
        Wx[k * XCOLS + c] = gate_kernel[k * GH + c];
    }
    for (int idx = tid; idx < 64 * H_DIM; idx += 256) {
        int k = idx >> 7, c = idx & 127;
        Wx[k * XCOLS + 256 + c] = cand_kernel[k * H_DIM + c];
    }
    if (tid < 256) bs[tid] = gate_bias[tid];
    if (tid < 128) bs[256 + tid] = cand_bias[tid];
    if (tid < 32)  items_s[tid] = item_his[b * T_DIM + t0 + tid];
    __syncthreads();

    // gather embedding rows for this tile
    for (int e = tid; e < 32 * 64; e += 256) {
        int r = e >> 6, k = e & 63;
        xs[e] = embedding[items_s[r] * 64 + k];
    }
    __syncthreads();

    // 4x12 register micro-tile per thread: rows {tr+8*ri}, cols {tc+32*ci}
    int tc = tid & 31;
    int tr = tid >> 5;
    float acc[4][12];
    #pragma unroll
    for (int ri = 0; ri < 4; ri++)
        #pragma unroll
        for (int ci = 0; ci < 12; ci++) acc[ri][ci] = 0.0f;

    #pragma unroll 4
    for (int k = 0; k < 64; k++) {
        float a0 = xs[(tr + 0)  * 64 + k];
        float a1 = xs[(tr + 8)  * 64 + k];
        float a2 = xs[(tr + 16) * 64 + k];
        float a3 = xs[(tr + 24) * 64 + k];
        float w[12];
        #pragma unroll
        for (int ci = 0; ci < 12; ci++) w[ci] = Wx[k * XCOLS + tc + 32 * ci];
        #pragma unroll
        for (int ci = 0; ci < 12; ci++) {
            acc[0][ci] = fmaf(a0, w[ci], acc[0][ci]);
            acc[1][ci] = fmaf(a1, w[ci], acc[1][ci]);
            acc[2][ci] = fmaf(a2, w[ci], acc[2][ci]);
            acc[3][ci] = fmaf(a3, w[ci], acc[3][ci]);
        }
    }

    #pragma unroll
    for (int ri = 0; ri < 4; ri++) {
        int t = t0 + tr + 8 * ri;
        float* dst = g_Xbuf + (size_t)(b * T_DIM + t) * XCOLS;
        #pragma unroll
        for (int ci = 0; ci < 12; ci++) {
            int c = tc + 32 * ci;
            dst[c] = acc[ri][ci] + bs[c];
        }
    }
}

// ---------------------------------------------------------------------------
// K2: persistent GRU recurrence. Each group = 4 batch rows (length-sorted).
// Weights transposed+padded in smem; h/rh/u in smem; 2 syncs per step.
// Thread j: gate column j (4 rows). For candidate: threads split rows 0-1 / 2-3,
// each handling hidden column i = tid & 127.
// ---------------------------------------------------------------------------
__global__ void __launch_bounds__(256, 1) gru_kernel(
    const int* __restrict__ seq_lens,
    const float* __restrict__ gate_kernel,
    const float* __restrict__ cand_kernel,
    float* __restrict__ out)
{
    extern __shared__ float sm[];
    float* Ug   = sm;                          // [256][KPAD]  Ug[j][k] = W_g[64+k][j]
    float* Uc   = Ug + GH * KPAD;              // [128][KPAD]  Uc[i][k] = W_c[64+k][i]
    float* h_s  = Uc + H_DIM * KPAD;           // [4][128]
    float* rh_s = h_s + RROWS * H_DIM;         // [4][128]
    float* u_s  = rh_s + RROWS * H_DIM;        // [4][128]
    __shared__ int s_g;
    __shared__ int s_b[RROWS];
    __shared__ int s_len[RROWS];

    int tid = threadIdx.x;

    // stage transposed recurrent weights (one-time per block)
    for (int idx = tid; idx < H_DIM * GH; idx += 256) {
        int k = idx >> 8, j = idx & 255;
        Ug[j * KPAD + k] = gate_kernel[(D_DIM + k) * GH + j];
    }
    for (int idx = tid; idx < H_DIM * H_DIM; idx += 256) {
        int k = idx >> 7, i = idx & 127;
        Uc[i * KPAD + k] = cand_kernel[(D_DIM + k) * H_DIM + i];
    }

    int j    = tid;
    int i    = tid & 127;
    int half = tid >> 7;                       // 0: cand rows 0,1 ; 1: cand rows 2,3
    const float4* Ug4 = (const float4*)(Ug + j * KPAD);
    const float4* Uc4 = (const float4*)(Uc + i * KPAD);
    const float4* h40 = (const float4*)(h_s);
    const float4* h41 = h40 + (H_DIM / 4);
    const float4* h42 = h41 + (H_DIM / 4);
    const float4* h43 = h42 + (H_DIM / 4);
    const float4* rhA4 = (const float4*)(rh_s + (2 * half) * H_DIM);
    const float4* rhB4 = rhA4 + (H_DIM / 4);
    float* hA = h_s + (2 * half) * H_DIM;
    float* hB = hA + H_DIM;
    __syncthreads();

    while (true) {
        if (tid == 0) s_g = atomicAdd(&g_counter, 1);
        __syncthreads();
        int g = s_g;
        if (g >= NGROUPS) break;

        if (tid < RROWS) {
            int r = g_perm[g * RROWS + tid];
            s_b[tid]   = r;
            s_len[tid] = min(max(seq_lens[r], 0), T_DIM);
        }
        for (int e = tid; e < RROWS * H_DIM; e += 256) h_s[e] = 0.0f;
        __syncthreads();

        int len0 = s_len[0], len1 = s_len[1], len2 = s_len[2], len3 = s_len[3];
        int L = max(max(len0, len1), max(len2, len3));
        int lenA = half ? len2 : len0;
        int lenB = half ? len3 : len1;

        const float* xg0 = g_Xbuf + s_b[0] * (T_DIM * XCOLS) + j;
        const float* xg1 = g_Xbuf + s_b[1] * (T_DIM * XCOLS) + j;
        const float* xg2 = g_Xbuf + s_b[2] * (T_DIM * XCOLS) + j;
        const float* xg3 = g_Xbuf + s_b[3] * (T_DIM * XCOLS) + j;
        const float* xcA = g_Xbuf + s_b[2 * half]     * (T_DIM * XCOLS) + 256 + i;
        const float* xcB = g_Xbuf + s_b[2 * half + 1] * (T_DIM * XCOLS) + 256 + i;

        for (int t = 0; t < L; t++) {
            // issue global loads early; consumed after the k-loops
            float vg0 = xg0[t * XCOLS];
            float vg1 = xg1[t * XCOLS];
            float vg2 = xg2[t * XCOLS];
            float vg3 = xg3[t * XCOLS];
            float vcA = xcA[t * XCOLS];
            float vcB = xcB[t * XCOLS];

            // gate GEMM: column j over 4 rows
            float a0 = 0.f, a1 = 0.f, a2 = 0.f, a3 = 0.f;
            #pragma unroll 8
            for (int k4 = 0; k4 < H_DIM / 4; k4++) {
                float4 w  = Ug4[k4];
                float4 v0 = h40[k4];
                a0 = fmaf(v0.x, w.x, a0); a0 = fmaf(v0.y, w.y, a0);
                a0 = fmaf(v0.z, w.z, a0); a0 = fmaf(v0.w, w.w, a0);
                float4 v1 = h41[k4];
                a1 = fmaf(v1.x, w.x, a1); a1 = fmaf(v1.y, w.y, a1);
                a1 = fmaf(v1.z, w.z, a1); a1 = fmaf(v1.w, w.w, a1);
                float4 v2 = h42[k4];
                a2 = fmaf(v2.x, w.x, a2); a2 = fmaf(v2.y, w.y, a2);
                a2 = fmaf(v2.z, w.z, a2); a2 = fmaf(v2.w, w.w, a2);
                float4 v3 = h43[k4];
                a3 = fmaf(v3.x, w.x, a3); a3 = fmaf(v3.y, w.y, a3);
                a3 = fmaf(v3.z, w.z, a3); a3 = fmaf(v3.w, w.w, a3);
            }
            float s0 = fast_sigmoid(a0 + vg0);
            float s1 = fast_sigmoid(a1 + vg1);
            float s2 = fast_sigmoid(a2 + vg2);
            float s3 = fast_sigmoid(a3 + vg3);

            if (half == 0) {           // r-gate columns 0..127
                rh_s[0 * H_DIM + j] = s0 * h_s[0 * H_DIM + j];
                rh_s[1 * H_DIM + j] = s1 * h_s[1 * H_DIM + j];
                rh_s[2 * H_DIM + j] = s2 * h_s[2 * H_DIM + j];
                rh_s[3 * H_DIM + j] = s3 * h_s[3 * H_DIM + j];
            } else {                   // u-gate columns 128..255 -> hidden col i
                u_s[0 * H_DIM + i] = s0;
                u_s[1 * H_DIM + i] = s1;
                u_s[2 * H_DIM + i] = s2;
                u_s[3 * H_DIM + i] = s3;
            }
            __syncthreads();

            // candidate GEMM: column i, 2 rows per thread-half
            float cA = 0.f, cB = 0.f;
            #pragma unroll 8
            for (int k4 = 0; k4 < H_DIM / 4; k4++) {
                float4 w  = Uc4[k4];
                float4 va = rhA4[k4];
                cA = fmaf(va.x, w.x, cA); cA = fmaf(va.y, w.y, cA);
                cA = fmaf(va.z, w.z, cA); cA = fmaf(va.w, w.w, cA);
                float4 vb = rhB4[k4];
                cB = fmaf(vb.x, w.x, cB); cB = fmaf(vb.y, w.y, cB);
                cB = fmaf(vb.z, w.z, cB); cB = fmaf(vb.w, w.w, cB);
            }
            {
                float c  = fast_tanh(cA + vcA);
                float u  = u_s[(2 * half) * H_DIM + i];
                float hv = hA[i];
                float hn = fmaf(u, hv - c, c);   // u*h + (1-u)*c
                if (t < lenA) hA[i] = hn;
            }
            {
                float c  = fast_tanh(cB + vcB);
                float u  = u_s[(2 * half + 1) * H_DIM + i];
                float hv = hB[i];
                float hn = fmaf(u, hv - c, c);
                if (t < lenB) hB[i] = hn;
            }
            __syncthreads();
        }

        out[s_b[2 * half]     * H_DIM + i] = hA[i];
        out[s_b[2 * half + 1] * H_DIM + i] = hB[i];
        __syncthreads();
    }
}

// ---------------------------------------------------------------------------
extern "C" void kernel_launch(void* const* d_in, const int* in_sizes, int n_in,
                              void* d_out, int out_size) {
    (void)in_sizes; (void)n_in; (void)out_size;
    const int*   item_his    = (const int*)  d_in[0];
    const int*   seq_lens    = (const int*)  d_in[1];
    const float* embedding   = (const float*)d_in[2];
    const float* gate_kernel = (const float*)d_in[3];
    const float* gate_bias   = (const float*)d_in[4];
    const float* cand_kernel = (const float*)d_in[5];
    const float* cand_bias   = (const float*)d_in[6];
    float*       out         = (float*)d_out;

    const int smem_proj = (64 * XCOLS + 32 * 64 + XCOLS) * 4;                    // 108032 B
    const int smem_gru  = (GH * KPAD + H_DIM * KPAD + 3 * RROWS * H_DIM) * 4;    // 208896 B
    cudaFuncSetAttribute(proj_kernel, cudaFuncAttributeMaxDynamicSharedMemorySize, smem_proj);
    cudaFuncSetAttribute(gru_kernel,  cudaFuncAttributeMaxDynamicSharedMemorySize, smem_gru);

    sort_kernel<<<1, 256>>>(seq_lens);
    proj_kernel<<<dim3(T_DIM / 32, B_DIM), 256, smem_proj>>>(
        item_his, seq_lens, embedding, gate_kernel, gate_bias, cand_kernel, cand_bias);
    gru_kernel<<<148, 256, smem_gru>>>(seq_lens, gate_kernel, cand_kernel, out);
}

// round 2
// speedup vs baseline: 1.0781x; 1.0781x over previous
#include <cuda_runtime.h>

#define B_DIM 1024
#define T_DIM 256
#define D_DIM 64
#define H_DIM 128
#define GH 256          // 2H
#define XCOLS 384       // 256 gate cols + 128 cand cols
#define RROWS 4
#define NGROUPS (B_DIM / RROWS)   // 256
#define KPAD 132        // padded k-stride (floats) for conflict-free LDS.128

// Scratch (device globals: no allocation allowed).
static __device__ float g_Xbuf[(size_t)B_DIM * T_DIM * XCOLS]; // ~402 MB
static __device__ int   g_perm[B_DIM];
static __device__ int   g_counter;

typedef unsigned long long ull;

__device__ __forceinline__ float fast_sigmoid(float z) {
    return __fdividef(1.0f, 1.0f + __expf(-z));
}
__device__ __forceinline__ float fast_tanh(float z) {
    return 1.0f - __fdividef(2.0f, __expf(2.0f * z) + 1.0f);
}

// packed fp32x2 helpers (Blackwell FFMA2 — PTX-only, exact fp32)
__device__ __forceinline__ void ffma2(ull& acc, ull a, ull b) {
    asm("fma.rn.f32x2 %0, %1, %2, %0;" : "+l"(acc) : "l"(a), "l"(b));
}
__device__ __forceinline__ ull pack2(float lo, float hi) {
    ull r;
    asm("mov.b64 %0, {%1, %2};" : "=l"(r) : "f"(lo), "f"(hi));
    return r;
}
__device__ __forceinline__ ull splat2(float v) {
    ull r;
    asm("mov.b64 %0, {%1, %1};" : "=l"(r) : "f"(v));
    return r;
}
__device__ __forceinline__ float hsum2(ull p) {
    float lo, hi;
    asm("mov.b64 {%0, %1}, %2;" : "=f"(lo), "=f"(hi) : "l"(p));
    return lo + hi;
}
__device__ __forceinline__ ull fadd2(ull a, ull b) {
    ull r;
    asm("add.rn.f32x2 %0, %1, %2;" : "=l"(r) : "l"(a), "l"(b));
    return r;
}

// ---------------------------------------------------------------------------
// K0: counting sort rows by seq_len (descending, LPT) + reset work counter.
// ---------------------------------------------------------------------------
__global__ void sort_kernel(const int* __restrict__ seq_lens) {
    __shared__ int hist[256];
    __shared__ int offs[256];
    int tid = threadIdx.x;
    hist[tid] = 0;
    __syncthreads();
    for (int r = tid; r < B_DIM; r += 256) {
        int L = seq_lens[r];
        L = min(max(L, 0), 255);
        atomicAdd(&hist[L], 1);
    }
    __syncthreads();
    if (tid == 0) {
        int run = 0;
        for (int k = 255; k >= 0; k--) { offs[k] = run; run += hist[k]; }
        g_counter = 0;
    }
    __syncthreads();
    for (int r = tid; r < B_DIM; r += 256) {
        int L = seq_lens[r];
        L = min(max(L, 0), 255);
        int pos = atomicAdd(&offs[L], 1);
        g_perm[pos] = r;
    }
}

// ---------------------------------------------------------------------------
// K1: projection with FFMA2.  Xbuf[b,t,0:256] = emb @ Wg_x + gb,
//                             Xbuf[b,t,256:384] = emb @ Wc_x + cb.
// Thread micro-tile: 4 rows (tr+8ri) x 6 column-PAIRS (2tc + 64ci).
// ---------------------------------------------------------------------------
__global__ void __launch_bounds__(256) proj_kernel(
    const int* __restrict__ item_his,
    const int* __restrict__ seq_lens,
    const float* __restrict__ embedding,
    const float* __restrict__ gate_kernel,
    const float* __restrict__ gate_bias,
    const float* __restrict__ cand_kernel,
    const float* __restrict__ cand_bias)
{
    extern __shared__ float sm[];
    float* Wx = sm;                    // [64][384]
    float* xs = Wx + 64 * XCOLS;       // [32][64]
    float* bs = xs + 32 * 64;          // [384]
    __shared__ int items_s[32];

    int b  = blockIdx.y;
    int t0 = blockIdx.x * 32;
    int len = seq_lens[b];
    if (t0 >= len) return;
    int tid = threadIdx.x;

    for (int idx = tid; idx < 64 * GH; idx += 256) {
        int k = idx >> 8, c = idx & 255;
        Wx[k * XCOLS + c] = gate_kernel[k * GH + c];
    }
    for (int idx = tid; idx < 64 * H_DIM; idx += 256) {
        int k = idx >> 7, c = idx & 127;
        Wx[k * XCOLS + 256 + c] = cand_kernel[k * H_DIM + c];
    }
    if (tid < 256) bs[tid] = gate_bias[tid];
    if (tid < 128) bs[256 + tid] = cand_bias[tid];
    if (tid < 32)  items_s[tid] = item_his[b * T_DIM + t0 + tid];
    __syncthreads();

    for (int e = tid; e < 32 * 64; e += 256) {
        int r = e >> 6, k = e & 63;
        xs[e] = embedding[items_s[r] * 64 + k];
    }
    __syncthreads();

    int tc = tid & 31;     // column pair base = 2*tc
    int tr = tid >> 5;     // row base
    ull acc[4][6];
    #pragma unroll
    for (int ri = 0; ri < 4; ri++)
        #pragma unroll
        for (int ci = 0; ci < 6; ci++) acc[ri][ci] = 0ULL;

    #pragma unroll 4
    for (int k = 0; k < 64; k++) {
        ull A0 = splat2(xs[(tr + 0)  * 64 + k]);
        ull A1 = splat2(xs[(tr + 8)  * 64 + k]);
        ull A2 = splat2(xs[(tr + 16) * 64 + k]);
        ull A3 = splat2(xs[(tr + 24) * 64 + k]);
        const float* wrow = Wx + k * XCOLS + 2 * tc;
        #pragma unroll
        for (int ci = 0; ci < 6; ci++) {
            ull w = *(const ull*)(wrow + 64 * ci);
            ffma2(acc[0][ci], A0, w);
            ffma2(acc[1][ci], A1, w);
            ffma2(acc[2][ci], A2, w);
            ffma2(acc[3][ci], A3, w);
        }
    }

    #pragma unroll
    for (int ri = 0; ri < 4; ri++) {
        int t = t0 + tr + 8 * ri;
        float* dst = g_Xbuf + (size_t)(b * T_DIM + t) * XCOLS;
        #pragma unroll
        for (int ci = 0; ci < 6; ci++) {
            int c = 2 * tc + 64 * ci;
            ull bias2 = *(const ull*)(bs + c);
            ull v = fadd2(acc[ri][ci], bias2);
            *(ull*)(dst + c) = v;
        }
    }
}

// ---------------------------------------------------------------------------
// K2: persistent GRU recurrence with FFMA2 (k-dimension packed).
// Group = 4 rows. Gate: thread j computes col j for 4 rows.
// Cand: k-split — thread (i, half) accumulates k in [64*half, 64*half+64)
// for all 4 rows; partials for non-owned rows go through smem; owner
// (half == row>>1) combines, applies tanh + update for rows 2*half, 2*half+1.
// ---------------------------------------------------------------------------
__global__ void __launch_bounds__(256, 1) gru_kernel(
    const int* __restrict__ seq_lens,
    const float* __restrict__ gate_kernel,
    const float* __restrict__ cand_kernel,
    float* __restrict__ out)
{
    extern __shared__ float sm[];
    float* Ug     = sm;                          // [256][KPAD]
    float* Uc     = Ug + GH * KPAD;              // [128][KPAD]
    float* h_s    = Uc + H_DIM * KPAD;           // [4][128]
    float* rh_s   = h_s + RROWS * H_DIM;         // [4][128]
    float* u_s    = rh_s + RROWS * H_DIM;        // [4][128]
    float* part_s = u_s + RROWS * H_DIM;         // [4][128]
    __shared__ int s_g;
    __shared__ int s_b[RROWS];
    __shared__ int s_len[RROWS];

    int tid = threadIdx.x;

    // stage transposed recurrent weights
    for (int idx = tid; idx < H_DIM * GH; idx += 256) {
        int k = idx >> 8, j = idx & 255;
        Ug[j * KPAD + k] = gate_kernel[(D_DIM + k) * GH + j];
    }
    for (int idx = tid; idx < H_DIM * H_DIM; idx += 256) {
        int k = idx >> 7, i = idx & 127;
        Uc[i * KPAD + k] = cand_kernel[(D_DIM + k) * H_DIM + i];
    }

    int j    = tid;
    int i    = tid & 127;
    int half = tid >> 7;
    const ulonglong2* Ug2 = (const ulonglong2*)(Ug + j * KPAD);
    const ulonglong2* Uc2 = (const ulonglong2*)(Uc + i * KPAD + half * 64);
    const ulonglong2* h20 = (const ulonglong2*)(h_s);
    const ulonglong2* h21 = h20 + (H_DIM / 4);
    const ulonglong2* h22 = h21 + (H_DIM / 4);
    const ulonglong2* h23 = h22 + (H_DIM / 4);
    const ulonglong2* rh20 = (const ulonglong2*)(rh_s + 0 * H_DIM + half * 64);
    const ulonglong2* rh21 = (const ulonglong2*)(rh_s + 1 * H_DIM + half * 64);
    const ulonglong2* rh22 = (const ulonglong2*)(rh_s + 2 * H_DIM + half * 64);
    const ulonglong2* rh23 = (const ulonglong2*)(rh_s + 3 * H_DIM + half * 64);
    float* hA = h_s + (2 * half) * H_DIM;        // owned rows
    float* hB = hA + H_DIM;
    __syncthreads();

    while (true) {
        if (tid == 0) s_g = atomicAdd(&g_counter, 1);
        __syncthreads();
        int g = s_g;
        if (g >= NGROUPS) break;

        if (tid < RROWS) {
            int r = g_perm[g * RROWS + tid];
            s_b[tid]   = r;
            s_len[tid] = min(max(seq_lens[r], 0), T_DIM);
        }
        for (int e = tid; e < RROWS * H_DIM; e += 256) h_s[e] = 0.0f;
        __syncthreads();

        int len0 = s_len[0], len1 = s_len[1], len2 = s_len[2], len3 = s_len[3];
        int L = max(max(len0, len1), max(len2, len3));
        int lenA = half ? len2 : len0;
        int lenB = half ? len3 : len1;

        const float* xg0 = g_Xbuf + s_b[0] * (T_DIM * XCOLS) + j;
        const float* xg1 = g_Xbuf + s_b[1] * (T_DIM * XCOLS) + j;
        const float* xg2 = g_Xbuf + s_b[2] * (T_DIM * XCOLS) + j;
        const float* xg3 = g_Xbuf + s_b[3] * (T_DIM * XCOLS) + j;
        const float* xcA = g_Xbuf + s_b[2 * half]     * (T_DIM * XCOLS) + 256 + i;
        const float* xcB = g_Xbuf + s_b[2 * half + 1] * (T_DIM * XCOLS) + 256 + i;

        for (int t = 0; t < L; t++) {
            // early global loads (consumed after the k-loops)
            float vg0 = xg0[t * XCOLS];
            float vg1 = xg1[t * XCOLS];
            float vg2 = xg2[t * XCOLS];
            float vg3 = xg3[t * XCOLS];
            float vcA = xcA[t * XCOLS];
            float vcB = xcB[t * XCOLS];

            // gate GEMM (col j, 4 rows) — packed k pairs
            ull a0 = pack2(vg0, 0.0f);
            ull a1 = pack2(vg1, 0.0f);
            ull a2 = pack2(vg2, 0.0f);
            ull a3 = pack2(vg3, 0.0f);
            #pragma unroll 8
            for (int k4 = 0; k4 < H_DIM / 4; k4++) {
                ulonglong2 w  = Ug2[k4];
                ulonglong2 v0 = h20[k4];
                ffma2(a0, v0.x, w.x); ffma2(a0, v0.y, w.y);
                ulonglong2 v1 = h21[k4];
                ffma2(a1, v1.x, w.x); ffma2(a1, v1.y, w.y);
                ulonglong2 v2 = h22[k4];
                ffma2(a2, v2.x, w.x); ffma2(a2, v2.y, w.y);
                ulonglong2 v3 = h23[k4];
                ffma2(a3, v3.x, w.x); ffma2(a3, v3.y, w.y);
            }
            float s0 = fast_sigmoid(hsum2(a0));
            float s1 = fast_sigmoid(hsum2(a1));
            float s2 = fast_sigmoid(hsum2(a2));
            float s3 = fast_sigmoid(hsum2(a3));

            if (half == 0) {           // r-gate columns 0..127
                rh_s[0 * H_DIM + j] = s0 * h_s[0 * H_DIM + j];
                rh_s[1 * H_DIM + j] = s1 * h_s[1 * H_DIM + j];
                rh_s[2 * H_DIM + j] = s2 * h_s[2 * H_DIM + j];
                rh_s[3 * H_DIM + j] = s3 * h_s[3 * H_DIM + j];
            } else {                   // u-gate columns 128..255
                u_s[0 * H_DIM + i] = s0;
                u_s[1 * H_DIM + i] = s1;
                u_s[2 * H_DIM + i] = s2;
                u_s[3 * H_DIM + i] = s3;
            }
            __syncthreads();

            // cand GEMM partials: k in [64*half, 64*half+64), all 4 rows
            ull c0 = 0ULL, c1 = 0ULL, c2 = 0ULL, c3 = 0ULL;
            #pragma unroll 8
            for (int k4 = 0; k4 < 16; k4++) {
                ulonglong2 w  = Uc2[k4];
                ulonglong2 v0 = rh20[k4];
                ffma2(c0, v0.x, w.x); ffma2(c0, v0.y, w.y);
                ulonglong2 v1 = rh21[k4];
                ffma2(c1, v1.x, w.x); ffma2(c1, v1.y, w.y);
                ulonglong2 v2 = rh22[k4];
                ffma2(c2, v2.x, w.x); ffma2(c2, v2.y, w.y);
                ulonglong2 v3 = rh23[k4];
                ffma2(c3, v3.x, w.x); ffma2(c3, v3.y, w.y);
            }
            float p0 = hsum2(c0), p1 = hsum2(c1), p2 = hsum2(c2), p3 = hsum2(c3);
            float ownA, ownB;
            if (half == 0) {           // owns rows 0,1; exports rows 2,3
                part_s[2 * H_DIM + i] = p2;
                part_s[3 * H_DIM + i] = p3;
                ownA = p0; ownB = p1;
            } else {                   // owns rows 2,3; exports rows 0,1
                part_s[0 * H_DIM + i] = p0;
                part_s[1 * H_DIM + i] = p1;
                ownA = p2; ownB = p3;
            }
            __syncthreads();

            {
                float c  = fast_tanh(ownA + part_s[(2 * half) * H_DIM + i] + vcA);
                float u  = u_s[(2 * half) * H_DIM + i];
                float hv = hA[i];
                float hn = fmaf(u, hv - c, c);   // u*h + (1-u)*c
                if (t < lenA) hA[i] = hn;
            }
            {
                float c  = fast_tanh(ownB + part_s[(2 * half + 1) * H_DIM + i] + vcB);
                float u  = u_s[(2 * half + 1) * H_DIM + i];
                float hv = hB[i];
                float hn = fmaf(u, hv - c, c);
                if (t < lenB) hB[i] = hn;
            }
            __syncthreads();
        }

        out[s_b[2 * half]     * H_DIM + i] = hA[i];
        out[s_b[2 * half + 1] * H_DIM + i] = hB[i];
        __syncthreads();
    }
}

// ---------------------------------------------------------------------------
extern "C" void kernel_launch(void* const* d_in, const int* in_sizes, int n_in,
                              void* d_out, int out_size) {
    (void)in_sizes; (void)n_in; (void)out_size;
    const int*   item_his    = (const int*)  d_in[0];
    const int*   seq_lens    = (const int*)  d_in[1];
    const float* embedding   = (const float*)d_in[2];
    const float* gate_kernel = (const float*)d_in[3];
    const float* gate_bias   = (const float*)d_in[4];
    const float* cand_kernel = (const float*)d_in[5];
    const float* cand_bias   = (const float*)d_in[6];
    float*       out         = (float*)d_out;

    const int smem_proj = (64 * XCOLS + 32 * 64 + XCOLS) * 4;                     // 108032 B
    const int smem_gru  = (GH * KPAD + H_DIM * KPAD + 4 * RROWS * H_DIM) * 4;     // 210944 B
    cudaFuncSetAttribute(proj_kernel, cudaFuncAttributeMaxDynamicSharedMemorySize, smem_proj);
    cudaFuncSetAttribute(gru_kernel,  cudaFuncAttributeMaxDynamicSharedMemorySize, smem_gru);

    sort_kernel<<<1, 256>>>(seq_lens);
    proj_kernel<<<dim3(T_DIM / 32, B_DIM), 256, smem_proj>>>(
        item_his, seq_lens, embedding, gate_kernel, gate_bias, cand_kernel, cand_bias);
    gru_kernel<<<148, 256, smem_gru>>>(seq_lens, gate_kernel, cand_kernel, out);
}